// round 4
// baseline (speedup 1.0000x reference)
#include <cuda_runtime.h>

typedef unsigned long long u64;

// Problem constants
#define BB 2
#define SS 1024
#define HH 8
#define DD 64
#define RR 32
#define KW 128
#define CC (HH*DD)        // 512 channels
#define ZLEN (4*KW+SS)    // 1536
#define TS 64             // s-tile per CTA
#define RH 16             // r rows per CTA
#define ZWIN (TS+KW)      // 192 loaded (191 needed)
#define ZSTRIDE 196       // padded row stride (words); 16B-aligned rows
#define NTHREADS 128

// ---- packed fp32x2 helpers (Blackwell FFMA2 path) ----
__device__ __forceinline__ u64 bcast2(float x) {
    u64 r; asm("mov.b64 %0, {%1, %1};" : "=l"(r) : "f"(x)); return r;
}
__device__ __forceinline__ void fma2(u64 &d, u64 a, u64 b) {
    // d.lo += a.lo*b.lo ; d.hi += a.hi*b.hi   (exact fp32 FMA per lane)
    asm("fma.rn.f32x2 %0, %1, %2, %0;" : "+l"(d) : "l"(a), "l"(b));
}
__device__ __forceinline__ float2 unpack2(u64 v) {
    float2 f; asm("mov.b64 {%0, %1}, %2;" : "=f"(f.x), "=f"(f.y) : "l"(v)); return f;
}

__global__ __launch_bounds__(NTHREADS, 4)
void convspe_kernel(const float* __restrict__ qg,
                    const float* __restrict__ kg,
                    const float* __restrict__ wq,
                    const float* __restrict__ wk,
                    const float* __restrict__ zg,
                    float* __restrict__ out)
{
    __shared__ __align__(16) float z_sm[RH * ZSTRIDE];   // 12.25 KB
    __shared__ __align__(16) float qk_sm[TS * DD * 2];   // 32 KB, interleaved (q,k)
    __shared__ __align__(16) float w2_sm[KW * 2];        // 1 KB, interleaved (wk,wq)

    const int tid   = threadIdx.x;
    const int stile = blockIdx.x;            // 0..15
    const int h     = blockIdx.y;            // 0..7
    const int bz    = blockIdx.z;            // 0..3
    const int b     = bz >> 1;
    const int r0    = (bz & 1) * RH;
    const int s0    = stile * TS;

    // ---- stage q/k tiles once, interleaved per (s,d): qk_sm[2*(s*D+d)] = {q,k} ----
    for (int idx = tid; idx < TS * DD / 4; idx += NTHREADS) {
        int row = idx >> 4;          // 0..63
        int c4  = idx & 15;          // 0..15
        int goff = (((b * SS + s0 + row) * HH + h) * DD) + c4 * 4;
        float4 q4 = *reinterpret_cast<const float4*>(qg + goff);
        float4 k4 = *reinterpret_cast<const float4*>(kg + goff);
        float2* dst = reinterpret_cast<float2*>(qk_sm) + row * DD + c4 * 4;
        dst[0] = make_float2(q4.x, k4.x);
        dst[1] = make_float2(q4.y, k4.y);
        dst[2] = make_float2(q4.z, k4.z);
        dst[3] = make_float2(q4.w, k4.w);
    }

    const int r  = tid & 15;         // 0..15  (z row)
    const int sg = tid >> 4;         // 0..7   (s group)
    const int i0 = sg * 8;

    u64 acc2d[8];                    // (accq, acck) pairs over d
    #pragma unroll
    for (int i = 0; i < 8; i++) acc2d[i] = 0ULL;   // bit pattern of (0.f, 0.f)

    for (int d = 0; d < DD; d++) {
        const int c = h * DD + d;

        __syncthreads();   // protect z_sm / w2_sm reuse (also covers qk staging on d==0)

        // ---- stage interleaved weight pairs: w2_sm[2t] = wk[c][t], w2_sm[2t+1] = wq[c][t] ----
        {
            float wkv = wk[c * KW + tid];     // coalesced across tid
            float wqv = wq[c * KW + tid];
            w2_sm[2 * tid]     = wkv;         // lo pairs with queries (cq += wk*z)
            w2_sm[2 * tid + 1] = wqv;         // hi pairs with keys    (ck += wq*z)
        }

        // ---- stage z window: rows r0..r0+15, cols K+s0 .. K+s0+191 ----
        for (int idx = tid; idx < RH * (ZWIN / 4); idx += NTHREADS) {
            int row = idx / (ZWIN / 4);          // /48
            int c4  = idx - row * (ZWIN / 4);    // %48
            int goff = ((b * RR + r0 + row) * CC + c) * ZLEN + (KW + s0) + c4 * 4;
            *reinterpret_cast<float4*>(z_sm + row * ZSTRIDE + c4 * 4) =
                *reinterpret_cast<const float4*>(zg + goff);
        }
        __syncthreads();

        const float* zrow = z_sm + r * ZSTRIDE + i0;   // 16B aligned
        const u64*   w2p  = reinterpret_cast<const u64*>(w2_sm);

        u64 c2[8];                       // per-d conv accumulators (cq, ck)
        #pragma unroll
        for (int i = 0; i < 8; i++) c2[i] = 0ULL;

        // ---- init broadcast window zz[0..14] = (z[p], z[p]) for p = 0..14 ----
        u64 zz[15];
        float carry;
        {
            float4 a0 = *reinterpret_cast<const float4*>(zrow);
            float4 a1 = *reinterpret_cast<const float4*>(zrow + 4);
            float4 a2 = *reinterpret_cast<const float4*>(zrow + 8);
            float4 a3 = *reinterpret_cast<const float4*>(zrow + 12);
            zz[0]=bcast2(a0.x);  zz[1]=bcast2(a0.y);  zz[2]=bcast2(a0.z);  zz[3]=bcast2(a0.w);
            zz[4]=bcast2(a1.x);  zz[5]=bcast2(a1.y);  zz[6]=bcast2(a1.z);  zz[7]=bcast2(a1.w);
            zz[8]=bcast2(a2.x);  zz[9]=bcast2(a2.y);  zz[10]=bcast2(a2.z); zz[11]=bcast2(a2.w);
            zz[12]=bcast2(a3.x); zz[13]=bcast2(a3.y); zz[14]=bcast2(a3.z);
            carry = a3.w;
        }

        #pragma unroll
        for (int tc = 0; tc < 16; tc++) {
            // prefetch next 8 z values (aligned LDS.128) while FMAs run
            float4 n0, n1;
            if (tc < 15) {
                n0 = *reinterpret_cast<const float4*>(zrow + tc * 8 + 16);
                n1 = *reinterpret_cast<const float4*>(zrow + tc * 8 + 20);
            }

            #pragma unroll
            for (int tt = 0; tt < 8; tt++) {
                u64 w2v = w2p[tc * 8 + tt];          // (wk[t], wq[t]) single LDS.64
                #pragma unroll
                for (int ii = 0; ii < 8; ii++)
                    fma2(c2[ii], w2v, zz[tt + ii]);  // 2 FMAs per instruction
            }

            if (tc < 15) {
                #pragma unroll
                for (int p = 0; p < 7; p++) zz[p] = zz[p + 8];   // renamed away by unroll
                zz[7]  = bcast2(carry);
                zz[8]  = bcast2(n0.x); zz[9]  = bcast2(n0.y);
                zz[10] = bcast2(n0.z); zz[11] = bcast2(n0.w);
                zz[12] = bcast2(n1.x); zz[13] = bcast2(n1.y);
                zz[14] = bcast2(n1.z);
                carry  = n1.w;
            }
        }

        // ---- epilogue: acc2d += c2 * (q, k) — one LDS.64 + one FFMA2 per s ----
        const u64* qkp = reinterpret_cast<const u64*>(qk_sm);
        #pragma unroll
        for (int ii = 0; ii < 8; ii++) {
            u64 qkv = qkp[(i0 + ii) * DD + d];
            fma2(acc2d[ii], c2[ii], qkv);
        }
    }

    // ---- write qhat then khat, each (B,S,H,R) row-major ----
    const int khat_off = BB * SS * HH * RR;
    #pragma unroll
    for (int ii = 0; ii < 8; ii++) {
        int s = s0 + i0 + ii;
        int o = ((b * SS + s) * HH + h) * RR + (r0 + r);
        float2 v = unpack2(acc2d[ii]);
        out[o]            = v.x;   // qhat (conv wk paired with queries)
        out[khat_off + o] = v.y;   // khat (conv wq paired with keys)
    }
}

extern "C" void kernel_launch(void* const* d_in, const int* in_sizes, int n_in,
                              void* d_out, int out_size)
{
    const float* queries = (const float*)d_in[0];
    const float* keys    = (const float*)d_in[1];
    const float* wq      = (const float*)d_in[2];
    const float* wk      = (const float*)d_in[3];
    const float* z       = (const float*)d_in[4];
    float* out = (float*)d_out;

    dim3 grid(SS / TS, HH, BB * 2);   // 16 x 8 x 4 = 512 CTAs
    dim3 block(NTHREADS);
    convspe_kernel<<<grid, block>>>(queries, keys, wq, wk, z, out);
}

// round 6
// speedup vs baseline: 2.8492x; 2.8492x over previous
#include <cuda_runtime.h>
#include <cstdint>

typedef uint32_t u32;

// Problem constants
#define BB 2
#define SS 1024
#define HH 8
#define DD 64
#define RR 32
#define KW 128
#define CC (HH*DD)          // 512
#define ZLEN (4*KW+SS)      // 1536
#define TS 64               // s per CTA
#define JW 192              // contraction width per d (TS + KW)
#define ZSTRIDE 196         // Z smem row stride in words (conflict-free, 16B-aligned)
#define QKSTRIDE 132        // QK smem row stride in words
#define NTHREADS 128

// dynamic smem carve-up (bytes)
#define Z_BYTES   (RR * ZSTRIDE * 4)        // 25088
#define QK_BYTES  (DD * QKSTRIDE * 4)       // 33792
#define W_BYTES   (2 * 256 * 4)             // 2048 (zero-padded filters)
#define DYN_BYTES (Z_BYTES + QK_BYTES + W_BYTES)   // 60928

__device__ __forceinline__ u32 cvt_tf32(float x) {
    u32 r; asm("cvt.rna.tf32.f32 %0, %1;" : "=r"(r) : "f"(x)); return r;
}

__device__ __forceinline__ void mma_tf32(float* c,
                                         u32 a0, u32 a1, u32 a2, u32 a3,
                                         u32 b0, u32 b1) {
    asm volatile(
        "mma.sync.aligned.m16n8k8.row.col.f32.tf32.tf32.f32 "
        "{%0,%1,%2,%3}, {%4,%5,%6,%7}, {%8,%9}, {%0,%1,%2,%3};"
        : "+f"(c[0]), "+f"(c[1]), "+f"(c[2]), "+f"(c[3])
        : "r"(a0), "r"(a1), "r"(a2), "r"(a3), "r"(b0), "r"(b1));
}

__global__ __launch_bounds__(NTHREADS, 3)
void convspe_mma_kernel(const float* __restrict__ qg,
                        const float* __restrict__ kg,
                        const float* __restrict__ wq,
                        const float* __restrict__ wk,
                        const float* __restrict__ zg,
                        float* __restrict__ out)
{
    extern __shared__ char dyn[];
    u32*   Zs   = reinterpret_cast<u32*>(dyn);                       // [32][196] tf32
    float* QK   = reinterpret_cast<float*>(dyn + Z_BYTES);           // [64][132] rows: 0-63 q, 64-127 k
    float* wpad = reinterpret_cast<float*>(dyn + Z_BYTES + QK_BYTES);// [2][256], band at [64,192)

    const int tid  = threadIdx.x;
    const int w    = tid >> 5;
    const int lane = tid & 31;
    const int g    = lane >> 2;       // row group 0..7
    const int qi   = lane & 3;        // quad index 0..3

    const int stile = blockIdx.x;     // 0..15
    const int h     = blockIdx.y;     // 0..7
    const int b     = blockIdx.z;     // 0..1
    const int s0    = stile * TS;
    const int cbase = h * DD;

    // ---- zero-fill wpad once (out-of-band entries stay 0 forever) ----
    #pragma unroll
    for (int i = 0; i < 4; i++) wpad[tid + i * 128] = 0.f;

    // ---- stage q/k transposed: QK[d][row] ----
    for (int idx = tid; idx < TS * 16; idx += NTHREADS) {  // 8 iters
        int srow = idx >> 4;
        int c4   = idx & 15;
        int goff = (((b * SS + s0 + srow) * HH + h) * DD) + c4 * 4;
        float4 q4 = *reinterpret_cast<const float4*>(qg + goff);
        float4 k4 = *reinterpret_cast<const float4*>(kg + goff);
        float qa[4] = {q4.x, q4.y, q4.z, q4.w};
        float ka[4] = {k4.x, k4.y, k4.z, k4.w};
        #pragma unroll
        for (int j = 0; j < 4; j++) {
            QK[(c4 * 4 + j) * QKSTRIDE + srow]      = qa[j];
            QK[(c4 * 4 + j) * QKSTRIDE + 64 + srow] = ka[j];
        }
    }

    // ---- per-warp constants ----
    const int f      = w >> 1;          // 0: qhat rows (filter wk), 1: khat rows (filter wq)
    const int c0     = (w & 1) * 4;     // chunk base (slb/8)
    const int m_base = w * 32;          // warp's first M row

    float acc[2][4][4];                 // [m-tile][n-tile][frag]
    #pragma unroll
    for (int t = 0; t < 2; t++)
        #pragma unroll
        for (int n = 0; n < 4; n++)
            #pragma unroll
            for (int i = 0; i < 4; i++) acc[t][n][i] = 0.f;

    const float* wp = wpad + f * 256;

    for (int d = 0; d < DD; d++) {
        const int c = cbase + d;

        __syncthreads();   // previous iteration's readers done (also covers init stores)

        // -- stage filters into band region [64,192): row0 = wk (qhat), row1 = wq (khat) --
        wpad[64 + tid]       = wk[c * KW + tid];
        wpad[256 + 64 + tid] = wq[c * KW + tid];

        // -- stage Z tile (32 x 192), tf32-rounded --
        #pragma unroll
        for (int i = 0; i < 12; i++) {
            int idx  = tid + i * NTHREADS;       // 0..1535
            int zrow = idx / 48;
            int gq   = idx - zrow * 48;
            float4 v = *reinterpret_cast<const float4*>(
                zg + ((size_t)((b * RR + zrow) * CC + c)) * ZLEN + KW + s0 + gq * 4);
            uint4 o;
            o.x = cvt_tf32(v.x); o.y = cvt_tf32(v.y);
            o.z = cvt_tf32(v.z); o.w = cvt_tf32(v.w);
            *reinterpret_cast<uint4*>(Zs + zrow * ZSTRIDE + gq * 4) = o;
        }
        __syncthreads();

        // -- per-d A-row scalars: q/k values for this thread's 4 rows --
        float qv00 = QK[d * QKSTRIDE + m_base + g];            // t=0, row
        float qv01 = QK[d * QKSTRIDE + m_base + g + 8];        // t=0, row+8
        float qv10 = QK[d * QKSTRIDE + m_base + 16 + g];       // t=1, row
        float qv11 = QK[d * QKSTRIDE + m_base + 16 + g + 8];   // t=1, row+8

        // -- 20 union chunks; m-tile0 active u<18, m-tile1 active u>=2 --
        #pragma unroll
        for (int u = 0; u < 20; u++) {
            const int kg = (c0 + u) * 8 + qi;      // global contraction col

            u32 b0[4], b1[4];
            #pragma unroll
            for (int n = 0; n < 4; n++) {
                const u32* zr = Zs + (n * 8 + g) * ZSTRIDE + kg;
                b0[n] = zr[0];
                b1[n] = zr[4];
            }

            if (u < 18) {   // m-tile 0
                int wi = 64 + 8 * u + qi - g;
                u32 a0 = cvt_tf32(qv00 * wp[wi]);
                u32 a2 = cvt_tf32(qv00 * wp[wi + 4]);
                u32 a1 = cvt_tf32(qv01 * wp[wi - 8]);
                u32 a3 = cvt_tf32(qv01 * wp[wi - 4]);
                #pragma unroll
                for (int n = 0; n < 4; n++)
                    mma_tf32(acc[0][n], a0, a1, a2, a3, b0[n], b1[n]);
            }
            if (u >= 2) {   // m-tile 1
                int wi = 64 + 8 * u + qi - g - 16;
                u32 a0 = cvt_tf32(qv10 * wp[wi]);
                u32 a2 = cvt_tf32(qv10 * wp[wi + 4]);
                u32 a1 = cvt_tf32(qv11 * wp[wi - 8]);
                u32 a3 = cvt_tf32(qv11 * wp[wi - 4]);
                #pragma unroll
                for (int n = 0; n < 4; n++)
                    mma_tf32(acc[1][n], a0, a1, a2, a3, b0[n], b1[n]);
            }
        }
    }

    // ---- epilogue: write accumulators straight to gmem ----
    // D frag layout: c0,c1 -> (row=g, col=2qi, 2qi+1), c2,c3 -> (row=g+8, same cols)
    const int khat_off = BB * SS * HH * RR;
    #pragma unroll
    for (int t = 0; t < 2; t++) {
        int row  = m_base + 16 * t + g;       // global M row (of its filter half)
        int srow = row & 63;
        float* obase = out + (f ? khat_off : 0)
                     + ((b * SS + s0 + srow) * HH + h) * RR;
        float* obase8 = obase + 8 * HH * RR;  // srow + 8
        #pragma unroll
        for (int n = 0; n < 4; n++) {
            int col = n * 8 + 2 * qi;
            *reinterpret_cast<float2*>(obase  + col) = make_float2(acc[t][n][0], acc[t][n][1]);
            *reinterpret_cast<float2*>(obase8 + col) = make_float2(acc[t][n][2], acc[t][n][3]);
        }
    }
}

extern "C" void kernel_launch(void* const* d_in, const int* in_sizes, int n_in,
                              void* d_out, int out_size)
{
    const float* queries = (const float*)d_in[0];
    const float* keys    = (const float*)d_in[1];
    const float* wq      = (const float*)d_in[2];
    const float* wk      = (const float*)d_in[3];
    const float* z       = (const float*)d_in[4];
    float* out = (float*)d_out;

    cudaFuncSetAttribute(convspe_mma_kernel,
                         cudaFuncAttributeMaxDynamicSharedMemorySize, DYN_BYTES);

    dim3 grid(SS / TS, HH, BB);   // 16 x 8 x 2 = 256 CTAs
    dim3 block(NTHREADS);
    convspe_mma_kernel<<<grid, block, DYN_BYTES>>>(queries, keys, wq, wk, z, out);
}